// round 14
// baseline (speedup 1.0000x reference)
#include <cuda_runtime.h>
#include <cuda_bf16.h>

#define FULLMASK 0xffffffffu
#define MAXL 32

// HierarchicalSoftmax. One warp per sample; two 16-step chunks, each a batched
// W-row load burst + 16-acc register butterfly that transposes step-sums onto
// lanes (lane l ends with the dot product of step l). Packed f32x2 FMAs.
//
// v14 critical-path shaves over the 12.7us champion:
//  - chase-first prologue: target load issued before embedding loads, so the
//    dependent target->path_nodes pointer chase overlaps the embedding fetch;
//  - bias prefetch: the scattered per-lane bias gather is issued right after
//    the mask ballot (depends only on my_node), removing a full scattered-load
//    latency from the post-butterfly tail;
//  - max-L1 carveout requested (kernel uses no smem).
//
// Path validity from data: Huffman root id 0 is the LAST valid entry of every
// path; padding is also 0 -> active[l] = (l<L) && (l==0 || node[l-1]!=0).

typedef unsigned long long u64;

__device__ __forceinline__ u64 ffma2(u64 a, u64 b, u64 c)
{
    u64 d;
    asm("fma.rn.f32x2 %0, %1, %2, %3;" : "=l"(d) : "l"(a), "l"(b), "l"(c));
    return d;
}

__device__ __forceinline__ float f32x2_hsum(u64 p)
{
    float lo, hi;
    asm("mov.b64 {%0, %1}, %2;" : "=f"(lo), "=f"(hi) : "l"(p));
    return lo + hi;
}

__device__ __forceinline__ float hs_dot16p(const ulonglong2* __restrict__ Wv,
                                           unsigned am, int base, int my_node,
                                           int lane,
                                           ulonglong2 ea, ulonglong2 eb,
                                           ulonglong2 ec, ulonglong2 ed)
{
    float acc[16];
    #pragma unroll
    for (int i = 0; i < 16; ++i) {
        float s = 0.0f;
        if ((am >> (base + i)) & 1u) {               // warp-uniform (prefix mask)
            int node = __shfl_sync(FULLMASK, my_node, base + i);
            const ulonglong2* w = Wv + (size_t)node * 128;
            ulonglong2 w0 = w[lane +  0];
            ulonglong2 w1 = w[lane + 32];
            ulonglong2 w2 = w[lane + 64];
            ulonglong2 w3 = w[lane + 96];
            u64 p = ffma2(ea.x, w0.x, 0ULL);
            p = ffma2(ea.y, w0.y, p);
            p = ffma2(eb.x, w1.x, p);
            p = ffma2(eb.y, w1.y, p);
            p = ffma2(ec.x, w2.x, p);
            p = ffma2(ec.y, w2.y, p);
            p = ffma2(ed.x, w3.x, p);
            p = ffma2(ed.y, w3.y, p);
            s = f32x2_hsum(p);
        }
        acc[i] = s;
    }
    // Butterfly: strides 8..1 reduce within each 16-lane half; afterwards lane l
    // holds the half-sum of step (l & 15). Stride-16 combine -> full dot product.
    #pragma unroll
    for (int h = 8; h >= 1; h >>= 1) {
        #pragma unroll
        for (int i = 0; i < h; ++i) {
            float v = acc[i], w = acc[i + h];
            float give = (lane & h) ? v : w;
            float got  = __shfl_xor_sync(FULLMASK, give, h);
            acc[i] = ((lane & h) ? w : v) + got;
        }
    }
    return acc[0] + __shfl_xor_sync(FULLMASK, acc[0], 16);
}

__global__ __launch_bounds__(128, 7)
void hs512_v14_kernel(const float* __restrict__ emb,
                      const float* __restrict__ W,
                      const float* __restrict__ bias,
                      const int*   __restrict__ target,
                      const int*   __restrict__ path_nodes,
                      const int*   __restrict__ path_dirs,
                      float*       __restrict__ out,
                      int B, int L)
{
    const int D16 = 512 / 4;                                   // 128 16B chunks/row
    int gw   = (blockIdx.x * blockDim.x + threadIdx.x) >> 5;   // one warp per sample
    int lane = threadIdx.x & 31;
    if (gw >= B) return;

    // ── Chase first: target load issued before anything else.
    int t = __ldg(target + gw);

    // Embedding loads (independent) fill the chase latency.
    const ulonglong2* ev = reinterpret_cast<const ulonglong2*>(emb) + (size_t)gw * D16;
    ulonglong2 ea = ev[lane +  0];
    ulonglong2 eb = ev[lane + 32];
    ulonglong2 ec = ev[lane + 64];
    ulonglong2 ed = ev[lane + 96];

    const int* nrow = path_nodes + (size_t)t * L;
    const int* drow = path_dirs  + (size_t)t * L;

    // Coalesced per-lane node/dir loads: lane l owns path step l.
    int my_node = (lane < L) ? __ldg(nrow + lane) : 0;
    int my_dir  = (lane < L) ? __ldg(drow + lane) : 0;

    // Active mask via shfl_up + ballot (root id 0 terminates the path).
    int prev = __shfl_up_sync(FULLMASK, my_node, 1);
    bool act = (lane < L) && (lane == 0 || prev != 0);
    unsigned am = __ballot_sync(FULLMASK, act);

    // Bias prefetch: scattered gather issued BEFORE the W bursts so its latency
    // is hidden under them instead of sitting on the post-butterfly tail.
    float my_bias = act ? __ldg(bias + my_node) : 0.0f;

    const ulonglong2* Wv = reinterpret_cast<const ulonglong2*>(W);

    // Chunk A: steps 0..15. Lane l gets dot of step (l & 15).
    float sA = hs_dot16p(Wv, am, 0, my_node, lane, ea, eb, ec, ed);

    // Chunk B: steps 16..31 — warp-uniform skip when the path is short.
    float sB = 0.0f;
    if (am >> 16)
        sB = hs_dot16p(Wv, am, 16, my_node, lane, ea, eb, ec, ed);

    // Epilogue: lane l holds step l's dot (sA for l<16, sB for l>=16 since
    // base + (l & 15) == l). One sigmoid per active lane; bias already in reg.
    float dotv = (lane < 16) ? sA : sB;
    float f = 1.0f;
    if (act) {
        float sc = dotv + my_bias;
        float sg = my_dir ? sc : -sc;
        f = __fdividef(1.0f, 1.0f + __expf(-sg));
    }
    #pragma unroll
    for (int o = 16; o >= 1; o >>= 1)
        f *= __shfl_xor_sync(FULLMASK, f, o);

    if (lane == 0) out[gw] = f;
}

// Generic fallback (any D, any L) — shape safety, not the hot path.
__global__ __launch_bounds__(256)
void hs_generic_kernel(const float* __restrict__ emb,
                       const float* __restrict__ W,
                       const float* __restrict__ bias,
                       const int*   __restrict__ target,
                       const int*   __restrict__ path_nodes,
                       const int*   __restrict__ path_dirs,
                       float*       __restrict__ out,
                       int B, int D, int L)
{
    int gw   = (blockIdx.x * blockDim.x + threadIdx.x) >> 5;
    int lane = threadIdx.x & 31;
    if (gw >= B) return;

    const float* e = emb + (size_t)gw * D;
    int t = __ldg(target + gw);
    const int* nrow = path_nodes + (size_t)t * L;
    const int* drow = path_dirs  + (size_t)t * L;

    float prod = 1.0f;
    for (int l = 0; l < L; ++l) {
        int node = __ldg(nrow + l);
        int dir  = __ldg(drow + l);
        const float* w = W + (size_t)node * D;
        float acc = 0.0f;
        for (int d = lane; d < D; d += 32)
            acc = fmaf(e[d], w[d], acc);
        #pragma unroll
        for (int off = 16; off > 0; off >>= 1)
            acc += __shfl_xor_sync(FULLMASK, acc, off);
        float s  = acc + __ldg(bias + node);
        float sg = dir ? s : -s;
        prod *= __fdividef(1.0f, 1.0f + __expf(-sg));
        if (node == 0) break;
    }
    if (lane == 0) out[gw] = prod;
}

extern "C" void kernel_launch(void* const* d_in, const int* in_sizes, int n_in,
                              void* d_out, int out_size)
{
    const float* emb    = (const float*)d_in[0];   // [B, D] f32
    const float* W      = (const float*)d_in[1];   // [V-1, D] f32
    const float* bias   = (const float*)d_in[2];   // [V-1] f32
    const int*   target = (const int*)  d_in[3];   // [B] i32
    const int*   nodes  = (const int*)  d_in[4];   // [V, L] i32
    const int*   dirs   = (const int*)  d_in[5];   // [V, L] i32
    // d_in[6] = path_mask: unused (validity derived from node==0 sentinel)

    int B = in_sizes[3];
    int D = in_sizes[0] / B;
    int V = in_sizes[2] + 1;
    int L = in_sizes[4] / V;
    float* out = (float*)d_out;

    // Kernel uses no shared memory: ask for the max-L1 carveout so the full
    // unified cache serves the hot W rows. Idempotent host-side call.
    cudaFuncSetAttribute(hs512_v14_kernel,
                         cudaFuncAttributePreferredSharedMemoryCarveout,
                         cudaSharedmemCarveoutMaxL1);

    if (D == 512 && L <= MAXL) {
        int threads = 128;                         // 4 warps = 4 samples per block
        int blocks  = (B * 32 + threads - 1) / threads;
        hs512_v14_kernel<<<blocks, threads>>>(emb, W, bias, target, nodes, dirs, out, B, L);
    } else {
        int threads = 256;
        int blocks  = (B * 32 + threads - 1) / threads;
        hs_generic_kernel<<<blocks, threads>>>(emb, W, bias, target, nodes, dirs, out, B, D, L);
    }
}